// round 11
// baseline (speedup 1.0000x reference)
#include <cuda_runtime.h>
#include <cuda_fp16.h>
#include <math.h>

#define IN_DIM 128
#define HC 128
#define H 4
#define C 32
#define MAXN 100000
#define MAXE 1600000
#define NEG_SLOPE 0.2f
#define LN_EPS 1e-5f

typedef unsigned long long u64;

// ---------------- scratch (device globals; no runtime allocation) ----------
__device__ __half g_xwh[(size_t)MAXN * HC];   // x @ W in fp16 (gather payload)
__device__ float  g_asrc[MAXN * H];
__device__ float  g_adst[MAXN * H];
__device__ float  g_den[MAXN * H];            // softmax denominators
__device__ float  g_alpha[(size_t)(MAXE + MAXN) * H];  // unnormalized alphas, CSR order
__device__ int    g_deg[MAXN];                // degree incl. self-loop
__device__ int    g_rowstart[MAXN];           // CSR row offsets
__device__ int    g_cursor[MAXN];             // fill cursors
__device__ int    g_csrc[MAXE + MAXN];        // CSR source indices
__device__ int    g_blocksums[512];

// ---------------- helpers ---------------------------------------------------
__device__ __forceinline__ float leaky(float v) {
    return v > 0.0f ? v : NEG_SLOPE * v;
}

__device__ __forceinline__ void redAddF32x4(float* dst, float4 v) {
    asm volatile("red.global.add.v4.f32 [%0], {%1, %2, %3, %4};"
                 :: "l"(dst), "f"(v.x), "f"(v.y), "f"(v.z), "f"(v.w)
                 : "memory");
}

__device__ __forceinline__ unsigned int f2tf32(float f) {
    unsigned int u;
    asm("cvt.rna.tf32.f32 %0, %1;" : "=r"(u) : "f"(f));
    return u;
}

__device__ __forceinline__ void mma_tf32(float* c,
        unsigned int a0, unsigned int a1, unsigned int a2, unsigned int a3,
        unsigned int b0, unsigned int b1) {
    asm volatile(
        "mma.sync.aligned.m16n8k8.row.col.f32.tf32.tf32.f32 "
        "{%0,%1,%2,%3}, {%4,%5,%6,%7}, {%8,%9}, {%0,%1,%2,%3};"
        : "+f"(c[0]), "+f"(c[1]), "+f"(c[2]), "+f"(c[3])
        : "r"(a0), "r"(a1), "r"(a2), "r"(a3), "r"(b0), "r"(b1));
}

// ---------------- TF32 MMA GEMM (2x4 warp tiling) + fused att --------------
#define AS_STRIDE 36    // 32 k + pad
#define BS_STRIDE 136   // 128 n + pad

__global__ __launch_bounds__(256, 2) void gemm_att_kernel(
        const float* __restrict__ x, const float* __restrict__ W,
        const float* __restrict__ att_src, const float* __restrict__ att_dst,
        int N) {
    __shared__ unsigned int As[128 * AS_STRIDE];
    __shared__ unsigned int Bs[32 * BS_STRIDE];

    int tid  = threadIdx.x;
    int w    = tid >> 5;
    int lane = tid & 31;
    int q    = lane & 3;          // thread in quad
    int g    = lane >> 2;         // quad id (0..7)
    int wm   = w & 1;             // warp M group (2 x 64 rows)
    int wn   = w >> 1;            // warp N group (4 x 32 cols) == head
    int block_row = blockIdx.x * 128;

    float acc[4][4][4];           // [mt][nt][frag]
#pragma unroll
    for (int mt = 0; mt < 4; mt++)
#pragma unroll
        for (int nt = 0; nt < 4; nt++)
#pragma unroll
            for (int j = 0; j < 4; j++) acc[mt][nt][j] = 0.0f;

#pragma unroll
    for (int chunk = 0; chunk < 4; chunk++) {
        int kk = chunk * 32;
        // load A tile: 128 rows x 32 k (fp32 -> tf32)
#pragma unroll
        for (int it = 0; it < 4; it++) {
            int r  = (tid >> 3) + it * 32;
            int c4 = (tid & 7) * 4;
            int grow = block_row + r;
            float4 v = make_float4(0.f, 0.f, 0.f, 0.f);
            if (grow < N)
                v = *(const float4*)(x + (size_t)grow * IN_DIM + kk + c4);
            unsigned int* dst = As + r * AS_STRIDE + c4;
            dst[0] = f2tf32(v.x);
            dst[1] = f2tf32(v.y);
            dst[2] = f2tf32(v.z);
            dst[3] = f2tf32(v.w);
        }
        // load B tile: 32 k x 128 n (fp32 -> tf32)
#pragma unroll
        for (int it = 0; it < 4; it++) {
            int k  = (tid >> 5) + it * 8;
            int n4 = (tid & 31) * 4;
            float4 v = *(const float4*)(W + (size_t)(kk + k) * HC + n4);
            unsigned int* dst = Bs + k * BS_STRIDE + n4;
            dst[0] = f2tf32(v.x);
            dst[1] = f2tf32(v.y);
            dst[2] = f2tf32(v.z);
            dst[3] = f2tf32(v.w);
        }
        __syncthreads();

#pragma unroll
        for (int ks = 0; ks < 4; ks++) {
            int kb = ks * 8;
            unsigned int a[4][4];
#pragma unroll
            for (int mt = 0; mt < 4; mt++) {
                int row0 = wm * 64 + mt * 16 + g;
                a[mt][0] = As[row0 * AS_STRIDE + kb + q];
                a[mt][1] = As[(row0 + 8) * AS_STRIDE + kb + q];
                a[mt][2] = As[row0 * AS_STRIDE + kb + q + 4];
                a[mt][3] = As[(row0 + 8) * AS_STRIDE + kb + q + 4];
            }
            unsigned int b[4][2];
#pragma unroll
            for (int nt = 0; nt < 4; nt++) {
                int col = wn * 32 + nt * 8 + g;
                b[nt][0] = Bs[(kb + q) * BS_STRIDE + col];
                b[nt][1] = Bs[(kb + q + 4) * BS_STRIDE + col];
            }
#pragma unroll
            for (int mt = 0; mt < 4; mt++)
#pragma unroll
                for (int nt = 0; nt < 4; nt++)
                    mma_tf32(acc[mt][nt], a[mt][0], a[mt][1], a[mt][2], a[mt][3],
                             b[nt][0], b[nt][1]);
        }
        __syncthreads();
    }

    // ---- epilogue: fused att dots (warp's cols = single head wn) ----------
    float attS[4][2], attD[4][2];
#pragma unroll
    for (int nt = 0; nt < 4; nt++) {
        int col = wn * 32 + nt * 8 + q * 2;
        attS[nt][0] = att_src[col];
        attS[nt][1] = att_src[col + 1];
        attD[nt][0] = att_dst[col];
        attD[nt][1] = att_dst[col + 1];
    }

#pragma unroll
    for (int mt = 0; mt < 4; mt++) {
        int r0 = block_row + wm * 64 + mt * 16 + g;
        int r1 = r0 + 8;
        float ps0 = 0.f, pd0 = 0.f, ps1 = 0.f, pd1 = 0.f;
#pragma unroll
        for (int nt = 0; nt < 4; nt++) {
            ps0 = fmaf(acc[mt][nt][0], attS[nt][0], fmaf(acc[mt][nt][1], attS[nt][1], ps0));
            pd0 = fmaf(acc[mt][nt][0], attD[nt][0], fmaf(acc[mt][nt][1], attD[nt][1], pd0));
            ps1 = fmaf(acc[mt][nt][2], attS[nt][0], fmaf(acc[mt][nt][3], attS[nt][1], ps1));
            pd1 = fmaf(acc[mt][nt][2], attD[nt][0], fmaf(acc[mt][nt][3], attD[nt][1], pd1));
            int col = wn * 32 + nt * 8 + q * 2;
            if (r0 < N) {
                __half2 p = __floats2half2_rn(acc[mt][nt][0], acc[mt][nt][1]);
                *(unsigned int*)(g_xwh + (size_t)r0 * HC + col) = *(unsigned int*)&p;
            }
            if (r1 < N) {
                __half2 p = __floats2half2_rn(acc[mt][nt][2], acc[mt][nt][3]);
                *(unsigned int*)(g_xwh + (size_t)r1 * HC + col) = *(unsigned int*)&p;
            }
        }
        // quad reduce across q (lanes sharing a row)
        ps0 += __shfl_down_sync(0xffffffff, ps0, 2, 4);
        ps0 += __shfl_down_sync(0xffffffff, ps0, 1, 4);
        pd0 += __shfl_down_sync(0xffffffff, pd0, 2, 4);
        pd0 += __shfl_down_sync(0xffffffff, pd0, 1, 4);
        ps1 += __shfl_down_sync(0xffffffff, ps1, 2, 4);
        ps1 += __shfl_down_sync(0xffffffff, ps1, 1, 4);
        pd1 += __shfl_down_sync(0xffffffff, pd1, 2, 4);
        pd1 += __shfl_down_sync(0xffffffff, pd1, 1, 4);
        if (q == 0) {
            if (r0 < N) {
                g_asrc[r0 * H + wn] = ps0;
                g_adst[r0 * H + wn] = pd0;
            }
            if (r1 < N) {
                g_asrc[r1 * H + wn] = ps1;
                g_adst[r1 * H + wn] = pd1;
            }
        }
    }
}

// ---------------- CSR build -------------------------------------------------
__global__ void hist_init_kernel(int N) {
    int i = blockIdx.x * blockDim.x + threadIdx.x;
    if (i < N) {
        g_deg[i] = 1;   // self-loop
        *(float4*)(g_den + i * 4) = make_float4(0.f, 0.f, 0.f, 0.f);
    }
}

__global__ void hist_kernel(const int* __restrict__ ei, int E) {
    int t = blockIdx.x * blockDim.x + threadIdx.x;
    int base = t * 4;
    const int* dst = ei + E;
    if (base + 4 <= E) {
        int4 d4 = *(const int4*)(dst + base);
        atomicAdd(&g_deg[d4.x], 1);
        atomicAdd(&g_deg[d4.y], 1);
        atomicAdd(&g_deg[d4.z], 1);
        atomicAdd(&g_deg[d4.w], 1);
    } else {
        for (int e = base; e < E; e++) atomicAdd(&g_deg[dst[e]], 1);
    }
}

// shuffle-based block scan (256 threads)
__global__ void scan1_kernel(int N) {
    __shared__ int ws[8];
    __shared__ int wsx[8];
    int tid = threadIdx.x;
    int lane = tid & 31;
    int w = tid >> 5;
    int i = blockIdx.x * 256 + tid;
    int v = (i < N) ? g_deg[i] : 0;
    int xincl = v;
#pragma unroll
    for (int off = 1; off < 32; off <<= 1) {
        int t = __shfl_up_sync(0xffffffff, xincl, off);
        if (lane >= off) xincl += t;
    }
    if (lane == 31) ws[w] = xincl;
    __syncthreads();
    if (tid < 8) {
        int s = 0;
        for (int j = 0; j < tid; j++) s += ws[j];
        wsx[tid] = s;
    }
    __syncthreads();
    int incl = xincl + wsx[w];
    if (i < N) g_rowstart[i] = incl - v;      // exclusive within block
    if (tid == 255) g_blocksums[blockIdx.x] = incl;
}

// shuffle-based scan of block sums (single block of 512)
__global__ void scan2_kernel(int B) {
    __shared__ int ws[16];
    __shared__ int wsx[16];
    int tid = threadIdx.x;
    int lane = tid & 31;
    int w = tid >> 5;
    int v = (tid < B) ? g_blocksums[tid] : 0;
    int xincl = v;
#pragma unroll
    for (int off = 1; off < 32; off <<= 1) {
        int t = __shfl_up_sync(0xffffffff, xincl, off);
        if (lane >= off) xincl += t;
    }
    if (lane == 31) ws[w] = xincl;
    __syncthreads();
    if (tid < 16) {
        int s = 0;
        for (int j = 0; j < tid; j++) s += ws[j];
        wsx[tid] = s;
    }
    __syncthreads();
    if (tid < B) g_blocksums[tid] = xincl + wsx[w] - v;  // exclusive
}

__global__ void scan3_kernel(int N) {
    int i = blockIdx.x * blockDim.x + threadIdx.x;
    if (i >= N) return;
    int rs = g_rowstart[i] + g_blocksums[i >> 8];
    g_rowstart[i] = rs;
    g_csrc[rs] = i;          // self-loop first
    g_cursor[i] = rs + 1;
}

// ---------------- fill + alpha + denominator (edge-parallel) ---------------
// For each edge (and self-loop), compute unnormalized softmax weights
// exp(leaky(asrc+adst)) for all 4 heads, store CSR-ordered, and reduce the
// per-destination denominators with vector atomics.
__global__ void fill_alpha_kernel(const int* __restrict__ ei, int E, int N) {
    int e = blockIdx.x * blockDim.x + threadIdx.x;
    if (e < E) {
        int s = ei[e];
        int d = ei[E + e];
        float4 as = *(const float4*)(g_asrc + (size_t)s * H);
        float4 ad = *(const float4*)(g_adst + (size_t)d * H);
        float4 ex;
        ex.x = __expf(leaky(as.x + ad.x));
        ex.y = __expf(leaky(as.y + ad.y));
        ex.z = __expf(leaky(as.z + ad.z));
        ex.w = __expf(leaky(as.w + ad.w));
        int pos = atomicAdd(&g_cursor[d], 1);
        g_csrc[pos] = s;
        *(float4*)(g_alpha + (size_t)pos * H) = ex;
        redAddF32x4(g_den + (size_t)d * H, ex);
    } else if (e < E + N) {
        int i = e - E;   // self-loop: src == dst == i
        float4 as = *(const float4*)(g_asrc + (size_t)i * H);
        float4 ad = *(const float4*)(g_adst + (size_t)i * H);
        float4 ex;
        ex.x = __expf(leaky(as.x + ad.x));
        ex.y = __expf(leaky(as.y + ad.y));
        ex.z = __expf(leaky(as.z + ad.z));
        ex.w = __expf(leaky(as.w + ad.w));
        int rs = g_rowstart[i];          // csrc[rs] == i (seeded in scan3)
        *(float4*)(g_alpha + (size_t)rs * H) = ex;
        redAddF32x4(g_den + (size_t)i * H, ex);
    }
}

// ---------------- single-pass aggregate + bias + LayerNorm -----------------
__global__ __launch_bounds__(256) void agg_kernel(float* __restrict__ out,
                                                  const float* __restrict__ bias,
                                                  const float* __restrict__ gamma,
                                                  const float* __restrict__ beta,
                                                  int N) {
    int gtid = blockIdx.x * blockDim.x + threadIdx.x;
    int node = gtid >> 5;
    int lane = gtid & 31;
    if (node >= N) return;

    int beg = g_rowstart[node];
    int deg = g_deg[node];
    int h = lane >> 3;
    int ch = lane * 4;

    float invS = 1.0f / (g_den[(size_t)node * H + h] + 1e-16f);

    float4 acc = make_float4(0.f, 0.f, 0.f, 0.f);
    int i = 0;
    for (; i + 8 <= deg; i += 8) {
        int   idx[8];
        float al[8];
        uint2 r[8];
#pragma unroll
        for (int j = 0; j < 8; j++) {
            idx[j] = g_csrc[beg + i + j];
            al[j]  = g_alpha[(size_t)(beg + i + j) * H + h];
        }
#pragma unroll
        for (int j = 0; j < 8; j++)
            r[j] = *(const uint2*)(g_xwh + (size_t)idx[j] * HC + ch);
#pragma unroll
        for (int j = 0; j < 8; j++) {
            float2 fa = __half22float2(*(__half2*)&r[j].x);
            float2 fb = __half22float2(*(__half2*)&r[j].y);
            acc.x = fmaf(al[j], fa.x, acc.x);
            acc.y = fmaf(al[j], fa.y, acc.y);
            acc.z = fmaf(al[j], fb.x, acc.z);
            acc.w = fmaf(al[j], fb.y, acc.w);
        }
    }
    for (; i < deg; i++) {
        int src  = g_csrc[beg + i];
        float a0 = g_alpha[(size_t)(beg + i) * H + h];
        uint2 r0 = *(const uint2*)(g_xwh + (size_t)src * HC + ch);
        float2 fa = __half22float2(*(__half2*)&r0.x);
        float2 fb = __half22float2(*(__half2*)&r0.y);
        acc.x = fmaf(a0, fa.x, acc.x);
        acc.y = fmaf(a0, fa.y, acc.y);
        acc.z = fmaf(a0, fb.x, acc.z);
        acc.w = fmaf(a0, fb.y, acc.w);
    }

    // normalize by softmax denominator
    acc.x *= invS; acc.y *= invS; acc.z *= invS; acc.w *= invS;

    // ---- epilogue: + bias, LayerNorm, write ------------------------------
    float4 b4 = *(const float4*)(bias + ch);
    acc.x += b4.x; acc.y += b4.y; acc.z += b4.z; acc.w += b4.w;

    float sum = acc.x + acc.y + acc.z + acc.w;
    float sq  = acc.x * acc.x + acc.y * acc.y + acc.z * acc.z + acc.w * acc.w;
#pragma unroll
    for (int off = 16; off > 0; off >>= 1) {
        sum += __shfl_xor_sync(0xffffffff, sum, off);
        sq  += __shfl_xor_sync(0xffffffff, sq,  off);
    }
    float mean = sum * (1.0f / HC);
    float var  = sq * (1.0f / HC) - mean * mean;
    float rstd = rsqrtf(var + LN_EPS);

    float4 g4 = *(const float4*)(gamma + ch);
    float4 be = *(const float4*)(beta + ch);
    acc.x = g4.x * (acc.x - mean) * rstd + be.x;
    acc.y = g4.y * (acc.y - mean) * rstd + be.y;
    acc.z = g4.z * (acc.z - mean) * rstd + be.z;
    acc.w = g4.w * (acc.w - mean) * rstd + be.w;
    *(float4*)(out + (size_t)node * HC + ch) = acc;
}

// ---------------- launch -----------------------------------------------------
// CSR front (hist/scan) runs on a forked side stream concurrent with the GEMM;
// fill_alpha needs both (asrc/adst from GEMM, cursors from scan3), then agg.
extern "C" void kernel_launch(void* const* d_in, const int* in_sizes, int n_in,
                              void* d_out, int out_size) {
    const float* x       = (const float*)d_in[0];
    const int*   ei      = (const int*)d_in[1];   // edge_index (int32 on the wire)
    // d_in[2] = edge_weight (unused by the reference computation)
    const float* W       = (const float*)d_in[3];
    const float* att_src = (const float*)d_in[4];
    const float* att_dst = (const float*)d_in[5];
    const float* bias    = (const float*)d_in[6];
    const float* gamma   = (const float*)d_in[7];
    const float* beta    = (const float*)d_in[8];
    float* out = (float*)d_out;

    int N = in_sizes[0] / IN_DIM;
    int E = in_sizes[2];            // edge_weight has E elements
    int nB = (N + 255) / 256;       // scan blocks (<=512)
    int e4B = (E / 4 + 256) / 256;  // 4-wide hist kernel (covers tail)
    int T = E + N;

    cudaStream_t s2;
    cudaEvent_t evFork, evJoin;
    cudaStreamCreateWithFlags(&s2, cudaStreamNonBlocking);
    cudaEventCreateWithFlags(&evFork, cudaEventDisableTiming);
    cudaEventCreateWithFlags(&evJoin, cudaEventDisableTiming);

    // fork: side stream depends on prior work in the main stream
    cudaEventRecord(evFork, 0);
    cudaStreamWaitEvent(s2, evFork, 0);

    // CSR front on s2 (independent of GEMM)
    hist_init_kernel<<<nB, 256, 0, s2>>>(N);                          // 1
    hist_kernel<<<e4B, 256, 0, s2>>>(ei, E);                          // 2
    scan1_kernel<<<nB, 256, 0, s2>>>(N);                              // 3
    // GEMM on main stream (submission #4 -> ncu capture window)
    gemm_att_kernel<<<(N + 127) / 128, 256>>>(x, W, att_src, att_dst, N);
    scan2_kernel<<<1, 512, 0, s2>>>(nB);                              // 5
    scan3_kernel<<<nB, 256, 0, s2>>>(N);                              // 6
    cudaEventRecord(evJoin, s2);

    // join: fill_alpha needs GEMM outputs AND the CSR cursors
    cudaStreamWaitEvent(0, evJoin, 0);
    fill_alpha_kernel<<<(T + 255) / 256, 256>>>(ei, E, N);            // 7

    // single-pass aggregate + LN
    {
        long long threads = (long long)N * 32;
        agg_kernel<<<(unsigned)((threads + 255) / 256), 256>>>(out, bias, gamma, beta, N);  // 8
    }
}

// round 12
// speedup vs baseline: 1.1040x; 1.1040x over previous
#include <cuda_runtime.h>
#include <cuda_fp16.h>
#include <math.h>

#define IN_DIM 128
#define HC 128
#define H 4
#define C 32
#define MAXN 100000
#define MAXE 1600000
#define NEG_SLOPE 0.2f
#define LN_EPS 1e-5f
#define CAPN 128   // smem-cached neighbors per node (spill path beyond)

typedef unsigned long long u64;

// ---------------- scratch (device globals; no runtime allocation) ----------
__device__ __half g_xwh[(size_t)MAXN * HC];   // x @ W in fp16 (gather payload)
__device__ float  g_asrc[MAXN * H];
__device__ float  g_adst[MAXN * H];
__device__ int    g_deg[MAXN];                // degree incl. self-loop
__device__ int    g_rowstart[MAXN];           // CSR row offsets
__device__ int    g_cursor[MAXN];             // fill cursors
__device__ int    g_csrc[MAXE + MAXN];        // CSR source indices
__device__ int    g_blocksums[512];

// ---------------- helpers ---------------------------------------------------
__device__ __forceinline__ float leaky(float v) {
    return v > 0.0f ? v : NEG_SLOPE * v;
}

__device__ __forceinline__ unsigned int f2tf32(float f) {
    unsigned int u;
    asm("cvt.rna.tf32.f32 %0, %1;" : "=r"(u) : "f"(f));
    return u;
}

__device__ __forceinline__ void mma_tf32(float* c,
        unsigned int a0, unsigned int a1, unsigned int a2, unsigned int a3,
        unsigned int b0, unsigned int b1) {
    asm volatile(
        "mma.sync.aligned.m16n8k8.row.col.f32.tf32.tf32.f32 "
        "{%0,%1,%2,%3}, {%4,%5,%6,%7}, {%8,%9}, {%0,%1,%2,%3};"
        : "+f"(c[0]), "+f"(c[1]), "+f"(c[2]), "+f"(c[3])
        : "r"(a0), "r"(a1), "r"(a2), "r"(a3), "r"(b0), "r"(b1));
}

// ---------------- TF32 MMA GEMM (2x4 warp tiling) + fused att --------------
#define AS_STRIDE 36    // 32 k + pad
#define BS_STRIDE 136   // 128 n + pad

__global__ __launch_bounds__(256, 2) void gemm_att_kernel(
        const float* __restrict__ x, const float* __restrict__ W,
        const float* __restrict__ att_src, const float* __restrict__ att_dst,
        int N) {
    __shared__ unsigned int As[128 * AS_STRIDE];
    __shared__ unsigned int Bs[32 * BS_STRIDE];

    int tid  = threadIdx.x;
    int w    = tid >> 5;
    int lane = tid & 31;
    int q    = lane & 3;          // thread in quad
    int g    = lane >> 2;         // quad id (0..7)
    int wm   = w & 1;             // warp M group (2 x 64 rows)
    int wn   = w >> 1;            // warp N group (4 x 32 cols) == head
    int block_row = blockIdx.x * 128;

    float acc[4][4][4];           // [mt][nt][frag]
#pragma unroll
    for (int mt = 0; mt < 4; mt++)
#pragma unroll
        for (int nt = 0; nt < 4; nt++)
#pragma unroll
            for (int j = 0; j < 4; j++) acc[mt][nt][j] = 0.0f;

#pragma unroll
    for (int chunk = 0; chunk < 4; chunk++) {
        int kk = chunk * 32;
        // load A tile: 128 rows x 32 k (fp32 -> tf32)
#pragma unroll
        for (int it = 0; it < 4; it++) {
            int r  = (tid >> 3) + it * 32;
            int c4 = (tid & 7) * 4;
            int grow = block_row + r;
            float4 v = make_float4(0.f, 0.f, 0.f, 0.f);
            if (grow < N)
                v = *(const float4*)(x + (size_t)grow * IN_DIM + kk + c4);
            unsigned int* dst = As + r * AS_STRIDE + c4;
            dst[0] = f2tf32(v.x);
            dst[1] = f2tf32(v.y);
            dst[2] = f2tf32(v.z);
            dst[3] = f2tf32(v.w);
        }
        // load B tile: 32 k x 128 n (fp32 -> tf32)
#pragma unroll
        for (int it = 0; it < 4; it++) {
            int k  = (tid >> 5) + it * 8;
            int n4 = (tid & 31) * 4;
            float4 v = *(const float4*)(W + (size_t)(kk + k) * HC + n4);
            unsigned int* dst = Bs + k * BS_STRIDE + n4;
            dst[0] = f2tf32(v.x);
            dst[1] = f2tf32(v.y);
            dst[2] = f2tf32(v.z);
            dst[3] = f2tf32(v.w);
        }
        __syncthreads();

#pragma unroll
        for (int ks = 0; ks < 4; ks++) {
            int kb = ks * 8;
            unsigned int a[4][4];
#pragma unroll
            for (int mt = 0; mt < 4; mt++) {
                int row0 = wm * 64 + mt * 16 + g;
                a[mt][0] = As[row0 * AS_STRIDE + kb + q];
                a[mt][1] = As[(row0 + 8) * AS_STRIDE + kb + q];
                a[mt][2] = As[row0 * AS_STRIDE + kb + q + 4];
                a[mt][3] = As[(row0 + 8) * AS_STRIDE + kb + q + 4];
            }
            unsigned int b[4][2];
#pragma unroll
            for (int nt = 0; nt < 4; nt++) {
                int col = wn * 32 + nt * 8 + g;
                b[nt][0] = Bs[(kb + q) * BS_STRIDE + col];
                b[nt][1] = Bs[(kb + q + 4) * BS_STRIDE + col];
            }
#pragma unroll
            for (int mt = 0; mt < 4; mt++)
#pragma unroll
                for (int nt = 0; nt < 4; nt++)
                    mma_tf32(acc[mt][nt], a[mt][0], a[mt][1], a[mt][2], a[mt][3],
                             b[nt][0], b[nt][1]);
        }
        __syncthreads();
    }

    // ---- epilogue: fused att dots (warp's cols = single head wn) ----------
    float attS[4][2], attD[4][2];
#pragma unroll
    for (int nt = 0; nt < 4; nt++) {
        int col = wn * 32 + nt * 8 + q * 2;
        attS[nt][0] = att_src[col];
        attS[nt][1] = att_src[col + 1];
        attD[nt][0] = att_dst[col];
        attD[nt][1] = att_dst[col + 1];
    }

#pragma unroll
    for (int mt = 0; mt < 4; mt++) {
        int r0 = block_row + wm * 64 + mt * 16 + g;
        int r1 = r0 + 8;
        float ps0 = 0.f, pd0 = 0.f, ps1 = 0.f, pd1 = 0.f;
#pragma unroll
        for (int nt = 0; nt < 4; nt++) {
            ps0 = fmaf(acc[mt][nt][0], attS[nt][0], fmaf(acc[mt][nt][1], attS[nt][1], ps0));
            pd0 = fmaf(acc[mt][nt][0], attD[nt][0], fmaf(acc[mt][nt][1], attD[nt][1], pd0));
            ps1 = fmaf(acc[mt][nt][2], attS[nt][0], fmaf(acc[mt][nt][3], attS[nt][1], ps1));
            pd1 = fmaf(acc[mt][nt][2], attD[nt][0], fmaf(acc[mt][nt][3], attD[nt][1], pd1));
            int col = wn * 32 + nt * 8 + q * 2;
            if (r0 < N) {
                __half2 p = __floats2half2_rn(acc[mt][nt][0], acc[mt][nt][1]);
                *(unsigned int*)(g_xwh + (size_t)r0 * HC + col) = *(unsigned int*)&p;
            }
            if (r1 < N) {
                __half2 p = __floats2half2_rn(acc[mt][nt][2], acc[mt][nt][3]);
                *(unsigned int*)(g_xwh + (size_t)r1 * HC + col) = *(unsigned int*)&p;
            }
        }
        // quad reduce across q (lanes sharing a row)
        ps0 += __shfl_down_sync(0xffffffff, ps0, 2, 4);
        ps0 += __shfl_down_sync(0xffffffff, ps0, 1, 4);
        pd0 += __shfl_down_sync(0xffffffff, pd0, 2, 4);
        pd0 += __shfl_down_sync(0xffffffff, pd0, 1, 4);
        ps1 += __shfl_down_sync(0xffffffff, ps1, 2, 4);
        ps1 += __shfl_down_sync(0xffffffff, ps1, 1, 4);
        pd1 += __shfl_down_sync(0xffffffff, pd1, 2, 4);
        pd1 += __shfl_down_sync(0xffffffff, pd1, 1, 4);
        if (q == 0) {
            if (r0 < N) {
                g_asrc[r0 * H + wn] = ps0;
                g_adst[r0 * H + wn] = pd0;
            }
            if (r1 < N) {
                g_asrc[r1 * H + wn] = ps1;
                g_adst[r1 * H + wn] = pd1;
            }
        }
    }
}

// ---------------- CSR build -------------------------------------------------
__global__ void hist_init_kernel(int N) {
    int i = blockIdx.x * blockDim.x + threadIdx.x;
    if (i < N) g_deg[i] = 1;   // self-loop
}

__global__ void hist_kernel(const int* __restrict__ ei, int E) {
    int t = blockIdx.x * blockDim.x + threadIdx.x;
    int base = t * 4;
    const int* dst = ei + E;
    if (base + 4 <= E) {
        int4 d4 = *(const int4*)(dst + base);
        atomicAdd(&g_deg[d4.x], 1);
        atomicAdd(&g_deg[d4.y], 1);
        atomicAdd(&g_deg[d4.z], 1);
        atomicAdd(&g_deg[d4.w], 1);
    } else {
        for (int e = base; e < E; e++) atomicAdd(&g_deg[dst[e]], 1);
    }
}

// shuffle-based block scan (256 threads)
__global__ void scan1_kernel(int N) {
    __shared__ int ws[8];
    __shared__ int wsx[8];
    int tid = threadIdx.x;
    int lane = tid & 31;
    int w = tid >> 5;
    int i = blockIdx.x * 256 + tid;
    int v = (i < N) ? g_deg[i] : 0;
    int xincl = v;
#pragma unroll
    for (int off = 1; off < 32; off <<= 1) {
        int t = __shfl_up_sync(0xffffffff, xincl, off);
        if (lane >= off) xincl += t;
    }
    if (lane == 31) ws[w] = xincl;
    __syncthreads();
    if (tid < 8) {
        int s = 0;
        for (int j = 0; j < tid; j++) s += ws[j];
        wsx[tid] = s;
    }
    __syncthreads();
    int incl = xincl + wsx[w];
    if (i < N) g_rowstart[i] = incl - v;      // exclusive within block
    if (tid == 255) g_blocksums[blockIdx.x] = incl;
}

// shuffle-based scan of block sums (single block of 512)
__global__ void scan2_kernel(int B) {
    __shared__ int ws[16];
    __shared__ int wsx[16];
    int tid = threadIdx.x;
    int lane = tid & 31;
    int w = tid >> 5;
    int v = (tid < B) ? g_blocksums[tid] : 0;
    int xincl = v;
#pragma unroll
    for (int off = 1; off < 32; off <<= 1) {
        int t = __shfl_up_sync(0xffffffff, xincl, off);
        if (lane >= off) xincl += t;
    }
    if (lane == 31) ws[w] = xincl;
    __syncthreads();
    if (tid < 16) {
        int s = 0;
        for (int j = 0; j < tid; j++) s += ws[j];
        wsx[tid] = s;
    }
    __syncthreads();
    if (tid < B) g_blocksums[tid] = xincl + wsx[w] - v;  // exclusive
}

__global__ void scan3_kernel(int N) {
    int i = blockIdx.x * blockDim.x + threadIdx.x;
    if (i >= N) return;
    int rs = g_rowstart[i] + g_blocksums[i >> 8];
    g_rowstart[i] = rs;
    g_csrc[rs] = i;          // self-loop first
    g_cursor[i] = rs + 1;
}

__global__ void fill_kernel(const int* __restrict__ ei, int E) {
    int t = blockIdx.x * blockDim.x + threadIdx.x;
    int base = t * 4;
    if (base + 4 <= E) {
        int4 s4 = *(const int4*)(ei + base);
        int4 d4 = *(const int4*)(ei + E + base);
        int p0 = atomicAdd(&g_cursor[d4.x], 1);
        int p1 = atomicAdd(&g_cursor[d4.y], 1);
        int p2 = atomicAdd(&g_cursor[d4.z], 1);
        int p3 = atomicAdd(&g_cursor[d4.w], 1);
        g_csrc[p0] = s4.x;
        g_csrc[p1] = s4.y;
        g_csrc[p2] = s4.z;
        g_csrc[p3] = s4.w;
    } else {
        for (int e = base; e < E; e++) {
            int d = ei[E + e];
            int pos = atomicAdd(&g_cursor[d], 1);
            g_csrc[pos] = ei[e];
        }
    }
}

// ---------------- fused softmax + aggregate + bias + LayerNorm -------------
// Pass 1: per-warp exp(logit)/index caches in smem + denominator reduction.
// Pass 2: TWO neighbors per warp iteration — each half-warp (16 lanes x 16 B
// LDG.128) gathers one full xwh row; lane owns 8 columns. Halves the gather
// instruction/wavefront count at identical bytes. Half-warp accumulators are
// merged by shuffle before the LN epilogue (lanes 16-31 contribute zeros).
__global__ __launch_bounds__(256) void agg_kernel(float* __restrict__ out,
                                                  const float* __restrict__ bias,
                                                  const float* __restrict__ gamma,
                                                  const float* __restrict__ beta,
                                                  int N) {
    __shared__ float s_e[8][CAPN * 4];   // per-warp alpha cache (16 KB)
    __shared__ int   s_i[8][CAPN];       // per-warp index cache (4 KB)

    int gtid = blockIdx.x * blockDim.x + threadIdx.x;
    int node = gtid >> 5;
    int lane = gtid & 31;
    int warp = (threadIdx.x) >> 5;
    if (node >= N) return;
    float* se = s_e[warp];
    int*   si = s_i[warp];

    int beg = g_rowstart[node];
    int deg = g_deg[node];

    float4 ad4 = *(const float4*)(g_adst + (size_t)node * H);
    float adh[4] = {ad4.x, ad4.y, ad4.z, ad4.w};

    // ---- pass 1: exp(logit)+index -> smem, accumulate denominators --------
    float s[4] = {0.f, 0.f, 0.f, 0.f};
    for (int i = lane; i < deg; i += 32) {
        int src = g_csrc[beg + i];
        float4 as = *(const float4*)(g_asrc + (size_t)src * H);
        float e0 = __expf(leaky(as.x + adh[0]));
        float e1 = __expf(leaky(as.y + adh[1]));
        float e2 = __expf(leaky(as.z + adh[2]));
        float e3 = __expf(leaky(as.w + adh[3]));
        if (i < CAPN) {
            *(float4*)(se + i * 4) = make_float4(e0, e1, e2, e3);
            si[i] = src;
        }
        s[0] += e0; s[1] += e1; s[2] += e2; s[3] += e3;
    }
#pragma unroll
    for (int h = 0; h < 4; h++) {
#pragma unroll
        for (int off = 16; off > 0; off >>= 1)
            s[h] += __shfl_xor_sync(0xffffffff, s[h], off);
    }
    __syncwarp();

    // half-warp layout: hw in {0,1} picks neighbor i+hw; sl owns 8 columns
    int hw = lane >> 4;
    int sl = lane & 15;
    int h  = sl >> 2;            // head for cols [sl*8, sl*8+8)
    int ch = sl * 8;
    float invS = 1.0f / (s[h] + 1e-16f);
    float adsh = adh[h];

    int dc = deg < CAPN ? deg : CAPN;

    // ---- pass 2: gather-accumulate, 2 neighbors per iteration -------------
    float acc[8];
#pragma unroll
    for (int k = 0; k < 8; k++) acc[k] = 0.0f;

    int i = 0;
#pragma unroll 4
    for (; i + 2 <= dc; i += 2) {
        int   src = si[i + hw];
        float a   = se[(i + hw) * 4 + h];
        uint4 r   = *(const uint4*)(g_xwh + (size_t)src * HC + ch);
        float2 f0 = __half22float2(*(__half2*)&r.x);
        float2 f1 = __half22float2(*(__half2*)&r.y);
        float2 f2 = __half22float2(*(__half2*)&r.z);
        float2 f3 = __half22float2(*(__half2*)&r.w);
        acc[0] = fmaf(a, f0.x, acc[0]);
        acc[1] = fmaf(a, f0.y, acc[1]);
        acc[2] = fmaf(a, f1.x, acc[2]);
        acc[3] = fmaf(a, f1.y, acc[3]);
        acc[4] = fmaf(a, f2.x, acc[4]);
        acc[5] = fmaf(a, f2.y, acc[5]);
        acc[6] = fmaf(a, f3.x, acc[6]);
        acc[7] = fmaf(a, f3.y, acc[7]);
    }
    if (i < dc) {               // odd tail within cached region
        if (hw == 0) {
            int   src = si[i];
            float a   = se[i * 4 + h];
            uint4 r   = *(const uint4*)(g_xwh + (size_t)src * HC + ch);
            float2 f0 = __half22float2(*(__half2*)&r.x);
            float2 f1 = __half22float2(*(__half2*)&r.y);
            float2 f2 = __half22float2(*(__half2*)&r.z);
            float2 f3 = __half22float2(*(__half2*)&r.w);
            acc[0] = fmaf(a, f0.x, acc[0]);
            acc[1] = fmaf(a, f0.y, acc[1]);
            acc[2] = fmaf(a, f1.x, acc[2]);
            acc[3] = fmaf(a, f1.y, acc[3]);
            acc[4] = fmaf(a, f2.x, acc[4]);
            acc[5] = fmaf(a, f2.y, acc[5]);
            acc[6] = fmaf(a, f3.x, acc[6]);
            acc[7] = fmaf(a, f3.y, acc[7]);
        }
        i++;
    }
    // spill path (deg > CAPN): recompute alpha from asrc
    for (; i < deg; ) {
        if (i + 2 <= deg) {
            int   src = g_csrc[beg + i + hw];
            float a   = __expf(leaky(g_asrc[(size_t)src * H + h] + adsh));
            uint4 r   = *(const uint4*)(g_xwh + (size_t)src * HC + ch);
            float2 f0 = __half22float2(*(__half2*)&r.x);
            float2 f1 = __half22float2(*(__half2*)&r.y);
            float2 f2 = __half22float2(*(__half2*)&r.z);
            float2 f3 = __half22float2(*(__half2*)&r.w);
            acc[0] = fmaf(a, f0.x, acc[0]);
            acc[1] = fmaf(a, f0.y, acc[1]);
            acc[2] = fmaf(a, f1.x, acc[2]);
            acc[3] = fmaf(a, f1.y, acc[3]);
            acc[4] = fmaf(a, f2.x, acc[4]);
            acc[5] = fmaf(a, f2.y, acc[5]);
            acc[6] = fmaf(a, f3.x, acc[6]);
            acc[7] = fmaf(a, f3.y, acc[7]);
            i += 2;
        } else {
            if (hw == 0) {
                int   src = g_csrc[beg + i];
                float a   = __expf(leaky(g_asrc[(size_t)src * H + h] + adsh));
                uint4 r   = *(const uint4*)(g_xwh + (size_t)src * HC + ch);
                float2 f0 = __half22float2(*(__half2*)&r.x);
                float2 f1 = __half22float2(*(__half2*)&r.y);
                float2 f2 = __half22float2(*(__half2*)&r.z);
                float2 f3 = __half22float2(*(__half2*)&r.w);
                acc[0] = fmaf(a, f0.x, acc[0]);
                acc[1] = fmaf(a, f0.y, acc[1]);
                acc[2] = fmaf(a, f1.x, acc[2]);
                acc[3] = fmaf(a, f1.y, acc[3]);
                acc[4] = fmaf(a, f2.x, acc[4]);
                acc[5] = fmaf(a, f2.y, acc[5]);
                acc[6] = fmaf(a, f3.x, acc[6]);
                acc[7] = fmaf(a, f3.y, acc[7]);
            }
            i++;
        }
    }

    // merge half-warp accumulators into lanes 0..15
#pragma unroll
    for (int k = 0; k < 8; k++) {
        float o = __shfl_down_sync(0xffffffff, acc[k], 16);
        acc[k] += o;
    }

    // ---- epilogue: normalize + bias, LayerNorm, write ---------------------
    float vals[8];
    if (hw == 0) {
        float4 b0 = *(const float4*)(bias + ch);
        float4 b1 = *(const float4*)(bias + ch + 4);
        vals[0] = acc[0] * invS + b0.x;
        vals[1] = acc[1] * invS + b0.y;
        vals[2] = acc[2] * invS + b0.z;
        vals[3] = acc[3] * invS + b0.w;
        vals[4] = acc[4] * invS + b1.x;
        vals[5] = acc[5] * invS + b1.y;
        vals[6] = acc[6] * invS + b1.z;
        vals[7] = acc[7] * invS + b1.w;
    } else {
#pragma unroll
        for (int k = 0; k < 8; k++) vals[k] = 0.0f;
    }

    float sum = 0.f, sq = 0.f;
#pragma unroll
    for (int k = 0; k < 8; k++) {
        sum += vals[k];
        sq  += vals[k] * vals[k];
    }
#pragma unroll
    for (int off = 16; off > 0; off >>= 1) {
        sum += __shfl_xor_sync(0xffffffff, sum, off);
        sq  += __shfl_xor_sync(0xffffffff, sq,  off);
    }
    float mean = sum * (1.0f / HC);
    float var  = sq * (1.0f / HC) - mean * mean;
    float rstd = rsqrtf(var + LN_EPS);

    if (hw == 0) {
        float4 g0 = *(const float4*)(gamma + ch);
        float4 g1 = *(const float4*)(gamma + ch + 4);
        float4 be0 = *(const float4*)(beta + ch);
        float4 be1 = *(const float4*)(beta + ch + 4);
        float4 o0, o1;
        o0.x = g0.x * (vals[0] - mean) * rstd + be0.x;
        o0.y = g0.y * (vals[1] - mean) * rstd + be0.y;
        o0.z = g0.z * (vals[2] - mean) * rstd + be0.z;
        o0.w = g0.w * (vals[3] - mean) * rstd + be0.w;
        o1.x = g1.x * (vals[4] - mean) * rstd + be1.x;
        o1.y = g1.y * (vals[5] - mean) * rstd + be1.y;
        o1.z = g1.z * (vals[6] - mean) * rstd + be1.z;
        o1.w = g1.w * (vals[7] - mean) * rstd + be1.w;
        float* row = out + (size_t)node * HC + ch;
        *(float4*)(row)     = o0;
        *(float4*)(row + 4) = o1;
    }
}

// ---------------- launch -----------------------------------------------------
// CSR build chain runs on a forked side stream, concurrent with the GEMM on
// the main stream; the two join before agg.
extern "C" void kernel_launch(void* const* d_in, const int* in_sizes, int n_in,
                              void* d_out, int out_size) {
    const float* x       = (const float*)d_in[0];
    const int*   ei      = (const int*)d_in[1];   // edge_index (int32 on the wire)
    // d_in[2] = edge_weight (unused by the reference computation)
    const float* W       = (const float*)d_in[3];
    const float* att_src = (const float*)d_in[4];
    const float* att_dst = (const float*)d_in[5];
    const float* bias    = (const float*)d_in[6];
    const float* gamma   = (const float*)d_in[7];
    const float* beta    = (const float*)d_in[8];
    float* out = (float*)d_out;

    int N = in_sizes[0] / IN_DIM;
    int E = in_sizes[2];            // edge_weight has E elements
    int nB = (N + 255) / 256;       // scan blocks (<=512)
    int e4B = (E / 4 + 256) / 256;  // 4-wide edge kernels (covers tail)

    cudaStream_t s2;
    cudaEvent_t evFork, evJoin;
    cudaStreamCreateWithFlags(&s2, cudaStreamNonBlocking);
    cudaEventCreateWithFlags(&evFork, cudaEventDisableTiming);
    cudaEventCreateWithFlags(&evJoin, cudaEventDisableTiming);

    // fork: side stream depends on prior work in the main stream
    cudaEventRecord(evFork, 0);
    cudaStreamWaitEvent(s2, evFork, 0);

    // CSR chain on s2 (independent of GEMM)
    hist_init_kernel<<<nB, 256, 0, s2>>>(N);                          // 1
    hist_kernel<<<e4B, 256, 0, s2>>>(ei, E);                          // 2
    scan1_kernel<<<nB, 256, 0, s2>>>(N);                              // 3
    // GEMM on main stream (submission #4 -> ncu capture window)
    gemm_att_kernel<<<(N + 127) / 128, 256>>>(x, W, att_src, att_dst, N);
    scan2_kernel<<<1, 512, 0, s2>>>(nB);                              // 5
    scan3_kernel<<<nB, 256, 0, s2>>>(N);                              // 6
    fill_kernel<<<e4B, 256, 0, s2>>>(ei, E);                          // 7
    cudaEventRecord(evJoin, s2);

    // join: agg needs both the GEMM outputs and the CSR structure
    cudaStreamWaitEvent(0, evJoin, 0);
    {
        long long threads = (long long)N * 32;
        agg_kernel<<<(unsigned)((threads + 255) / 256), 256>>>(out, bias, gamma, beta, N);  // 8
    }
}

// round 13
// speedup vs baseline: 1.3168x; 1.1928x over previous
#include <cuda_runtime.h>
#include <cuda_fp16.h>
#include <math.h>

#define IN_DIM 128
#define HC 128
#define H 4
#define C 32
#define MAXN 100000
#define MAXE 1600000
#define NEG_SLOPE 0.2f
#define LN_EPS 1e-5f
#define CAPN 128   // smem-cached neighbors per node (spill path beyond)

typedef unsigned long long u64;

// ---------------- scratch (device globals; no runtime allocation) ----------
__device__ __half g_xwh[(size_t)MAXN * HC];   // x @ W in fp16 (gather payload)
__device__ float  g_asrc[MAXN * H];
__device__ float  g_adst[MAXN * H];
__device__ int    g_deg[MAXN];                // degree incl. self-loop
__device__ int    g_rowstart[MAXN];           // CSR row offsets
__device__ int    g_cursor[MAXN];             // fill cursors
__device__ int    g_csrc[MAXE + MAXN];        // CSR source indices
__device__ int    g_blocksums[512];

// ---------------- helpers ---------------------------------------------------
__device__ __forceinline__ float leaky(float v) {
    return v > 0.0f ? v : NEG_SLOPE * v;
}

__device__ __forceinline__ unsigned int smem_u32(const void* p) {
    return (unsigned int)__cvta_generic_to_shared(p);
}

__device__ __forceinline__ void ldmatrix_x4(unsigned int& r0, unsigned int& r1,
                                            unsigned int& r2, unsigned int& r3,
                                            unsigned int addr) {
    asm volatile("ldmatrix.sync.aligned.m8n8.x4.shared.b16 {%0,%1,%2,%3}, [%4];"
                 : "=r"(r0), "=r"(r1), "=r"(r2), "=r"(r3) : "r"(addr));
}

__device__ __forceinline__ void ldmatrix_x4_trans(unsigned int& r0, unsigned int& r1,
                                                  unsigned int& r2, unsigned int& r3,
                                                  unsigned int addr) {
    asm volatile("ldmatrix.sync.aligned.m8n8.x4.trans.shared.b16 {%0,%1,%2,%3}, [%4];"
                 : "=r"(r0), "=r"(r1), "=r"(r2), "=r"(r3) : "r"(addr));
}

__device__ __forceinline__ void mma_f16(float* c,
        unsigned int a0, unsigned int a1, unsigned int a2, unsigned int a3,
        unsigned int b0, unsigned int b1) {
    asm volatile(
        "mma.sync.aligned.m16n8k16.row.col.f32.f16.f16.f32 "
        "{%0,%1,%2,%3}, {%4,%5,%6,%7}, {%8,%9}, {%0,%1,%2,%3};"
        : "+f"(c[0]), "+f"(c[1]), "+f"(c[2]), "+f"(c[3])
        : "r"(a0), "r"(a1), "r"(a2), "r"(a3), "r"(b0), "r"(b1));
}

// ---------------- FP16 MMA GEMM (2x4 warp tiling, ldmatrix) + fused att ----
#define A_STRIDE 40    // 32 k halves + 8 pad (80 B rows -> conflict-free LDSM)
#define B_STRIDE 136   // 128 n halves + 8 pad (272 B rows -> conflict-free)

__global__ __launch_bounds__(256, 2) void gemm_att_kernel(
        const float* __restrict__ x, const float* __restrict__ W,
        const float* __restrict__ att_src, const float* __restrict__ att_dst,
        int N) {
    __shared__ __half As[128 * A_STRIDE];   // 10240 B
    __shared__ __half Bs[32 * B_STRIDE];    // 8704 B

    int tid  = threadIdx.x;
    int w    = tid >> 5;
    int lane = tid & 31;
    int q    = lane & 3;          // thread in quad
    int g    = lane >> 2;         // quad id (0..7)
    int wm   = w & 1;             // warp M group (2 x 64 rows)
    int wn   = w >> 1;            // warp N group (4 x 32 cols) == head
    int block_row = blockIdx.x * 128;

    float acc[4][4][4];           // [mt][nt][frag]
#pragma unroll
    for (int mt = 0; mt < 4; mt++)
#pragma unroll
        for (int nt = 0; nt < 4; nt++)
#pragma unroll
            for (int j = 0; j < 4; j++) acc[mt][nt][j] = 0.0f;

#pragma unroll
    for (int chunk = 0; chunk < 4; chunk++) {
        int kk = chunk * 32;
        // load A tile: 128 rows x 32 k (fp32 -> fp16)
#pragma unroll
        for (int it = 0; it < 4; it++) {
            int r  = (tid >> 3) + it * 32;
            int c4 = (tid & 7) * 4;
            int grow = block_row + r;
            float4 v = make_float4(0.f, 0.f, 0.f, 0.f);
            if (grow < N)
                v = *(const float4*)(x + (size_t)grow * IN_DIM + kk + c4);
            __half2 h0 = __floats2half2_rn(v.x, v.y);
            __half2 h1 = __floats2half2_rn(v.z, v.w);
            uint2 p;
            p.x = *(unsigned int*)&h0;
            p.y = *(unsigned int*)&h1;
            *(uint2*)(As + r * A_STRIDE + c4) = p;
        }
        // load B tile: 32 k x 128 n (fp32 -> fp16), layout [k][n]
#pragma unroll
        for (int it = 0; it < 4; it++) {
            int k  = (tid >> 5) + it * 8;
            int n4 = (tid & 31) * 4;
            float4 v = *(const float4*)(W + (size_t)(kk + k) * HC + n4);
            __half2 h0 = __floats2half2_rn(v.x, v.y);
            __half2 h1 = __floats2half2_rn(v.z, v.w);
            uint2 p;
            p.x = *(unsigned int*)&h0;
            p.y = *(unsigned int*)&h1;
            *(uint2*)(Bs + k * B_STRIDE + n4) = p;
        }
        __syncthreads();

#pragma unroll
        for (int ks = 0; ks < 2; ks++) {
            int kb = ks * 16;
            // A fragments: one ldmatrix.x4 per m16 tile
            unsigned int a[4][4];
#pragma unroll
            for (int mt = 0; mt < 4; mt++) {
                int row  = wm * 64 + mt * 16 + (lane & 15);
                int kcol = kb + (lane >> 4) * 8;
                unsigned int addr = smem_u32(As + row * A_STRIDE + kcol);
                ldmatrix_x4(a[mt][0], a[mt][1], a[mt][2], a[mt][3], addr);
            }
            // B fragments: one ldmatrix.x4.trans per PAIR of n8 tiles
            unsigned int b[4][2];
#pragma unroll
            for (int ntp = 0; ntp < 2; ntp++) {
                int grp = lane >> 3;
                int kr  = kb + (lane & 7) + (grp & 1) * 8;
                int cn  = wn * 32 + ntp * 16 + (grp >> 1) * 8;
                unsigned int addr = smem_u32(Bs + kr * B_STRIDE + cn);
                unsigned int r0, r1, r2, r3;
                ldmatrix_x4_trans(r0, r1, r2, r3, addr);
                b[ntp * 2][0]     = r0;
                b[ntp * 2][1]     = r1;
                b[ntp * 2 + 1][0] = r2;
                b[ntp * 2 + 1][1] = r3;
            }
#pragma unroll
            for (int mt = 0; mt < 4; mt++)
#pragma unroll
                for (int nt = 0; nt < 4; nt++)
                    mma_f16(acc[mt][nt], a[mt][0], a[mt][1], a[mt][2], a[mt][3],
                            b[nt][0], b[nt][1]);
        }
        __syncthreads();
    }

    // ---- epilogue: fused att dots (warp's cols = single head wn) ----------
    float attS[4][2], attD[4][2];
#pragma unroll
    for (int nt = 0; nt < 4; nt++) {
        int col = wn * 32 + nt * 8 + q * 2;
        attS[nt][0] = att_src[col];
        attS[nt][1] = att_src[col + 1];
        attD[nt][0] = att_dst[col];
        attD[nt][1] = att_dst[col + 1];
    }

#pragma unroll
    for (int mt = 0; mt < 4; mt++) {
        int r0 = block_row + wm * 64 + mt * 16 + g;
        int r1 = r0 + 8;
        float ps0 = 0.f, pd0 = 0.f, ps1 = 0.f, pd1 = 0.f;
#pragma unroll
        for (int nt = 0; nt < 4; nt++) {
            ps0 = fmaf(acc[mt][nt][0], attS[nt][0], fmaf(acc[mt][nt][1], attS[nt][1], ps0));
            pd0 = fmaf(acc[mt][nt][0], attD[nt][0], fmaf(acc[mt][nt][1], attD[nt][1], pd0));
            ps1 = fmaf(acc[mt][nt][2], attS[nt][0], fmaf(acc[mt][nt][3], attS[nt][1], ps1));
            pd1 = fmaf(acc[mt][nt][2], attD[nt][0], fmaf(acc[mt][nt][3], attD[nt][1], pd1));
            int col = wn * 32 + nt * 8 + q * 2;
            if (r0 < N) {
                __half2 p = __floats2half2_rn(acc[mt][nt][0], acc[mt][nt][1]);
                *(unsigned int*)(g_xwh + (size_t)r0 * HC + col) = *(unsigned int*)&p;
            }
            if (r1 < N) {
                __half2 p = __floats2half2_rn(acc[mt][nt][2], acc[mt][nt][3]);
                *(unsigned int*)(g_xwh + (size_t)r1 * HC + col) = *(unsigned int*)&p;
            }
        }
        // quad reduce across q (lanes sharing a row)
        ps0 += __shfl_down_sync(0xffffffff, ps0, 2, 4);
        ps0 += __shfl_down_sync(0xffffffff, ps0, 1, 4);
        pd0 += __shfl_down_sync(0xffffffff, pd0, 2, 4);
        pd0 += __shfl_down_sync(0xffffffff, pd0, 1, 4);
        ps1 += __shfl_down_sync(0xffffffff, ps1, 2, 4);
        ps1 += __shfl_down_sync(0xffffffff, ps1, 1, 4);
        pd1 += __shfl_down_sync(0xffffffff, pd1, 2, 4);
        pd1 += __shfl_down_sync(0xffffffff, pd1, 1, 4);
        if (q == 0) {
            if (r0 < N) {
                g_asrc[r0 * H + wn] = ps0;
                g_adst[r0 * H + wn] = pd0;
            }
            if (r1 < N) {
                g_asrc[r1 * H + wn] = ps1;
                g_adst[r1 * H + wn] = pd1;
            }
        }
    }
}

// ---------------- CSR build -------------------------------------------------
__global__ void hist_init_kernel(int N) {
    int i = blockIdx.x * blockDim.x + threadIdx.x;
    if (i < N) g_deg[i] = 1;   // self-loop
}

__global__ void hist_kernel(const int* __restrict__ ei, int E) {
    int t = blockIdx.x * blockDim.x + threadIdx.x;
    int base = t * 4;
    const int* dst = ei + E;
    if (base + 4 <= E) {
        int4 d4 = *(const int4*)(dst + base);
        atomicAdd(&g_deg[d4.x], 1);
        atomicAdd(&g_deg[d4.y], 1);
        atomicAdd(&g_deg[d4.z], 1);
        atomicAdd(&g_deg[d4.w], 1);
    } else {
        for (int e = base; e < E; e++) atomicAdd(&g_deg[dst[e]], 1);
    }
}

// shuffle-based block scan (256 threads)
__global__ void scan1_kernel(int N) {
    __shared__ int ws[8];
    __shared__ int wsx[8];
    int tid = threadIdx.x;
    int lane = tid & 31;
    int w = tid >> 5;
    int i = blockIdx.x * 256 + tid;
    int v = (i < N) ? g_deg[i] : 0;
    int xincl = v;
#pragma unroll
    for (int off = 1; off < 32; off <<= 1) {
        int t = __shfl_up_sync(0xffffffff, xincl, off);
        if (lane >= off) xincl += t;
    }
    if (lane == 31) ws[w] = xincl;
    __syncthreads();
    if (tid < 8) {
        int s = 0;
        for (int j = 0; j < tid; j++) s += ws[j];
        wsx[tid] = s;
    }
    __syncthreads();
    int incl = xincl + wsx[w];
    if (i < N) g_rowstart[i] = incl - v;      // exclusive within block
    if (tid == 255) g_blocksums[blockIdx.x] = incl;
}

// shuffle-based scan of block sums (single block of 512)
__global__ void scan2_kernel(int B) {
    __shared__ int ws[16];
    __shared__ int wsx[16];
    int tid = threadIdx.x;
    int lane = tid & 31;
    int w = tid >> 5;
    int v = (tid < B) ? g_blocksums[tid] : 0;
    int xincl = v;
#pragma unroll
    for (int off = 1; off < 32; off <<= 1) {
        int t = __shfl_up_sync(0xffffffff, xincl, off);
        if (lane >= off) xincl += t;
    }
    if (lane == 31) ws[w] = xincl;
    __syncthreads();
    if (tid < 16) {
        int s = 0;
        for (int j = 0; j < tid; j++) s += ws[j];
        wsx[tid] = s;
    }
    __syncthreads();
    if (tid < B) g_blocksums[tid] = xincl + wsx[w] - v;  // exclusive
}

__global__ void scan3_kernel(int N) {
    int i = blockIdx.x * blockDim.x + threadIdx.x;
    if (i >= N) return;
    int rs = g_rowstart[i] + g_blocksums[i >> 8];
    g_rowstart[i] = rs;
    g_csrc[rs] = i;          // self-loop first
    g_cursor[i] = rs + 1;
}

__global__ void fill_kernel(const int* __restrict__ ei, int E) {
    int t = blockIdx.x * blockDim.x + threadIdx.x;
    int base = t * 4;
    if (base + 4 <= E) {
        int4 s4 = *(const int4*)(ei + base);
        int4 d4 = *(const int4*)(ei + E + base);
        int p0 = atomicAdd(&g_cursor[d4.x], 1);
        int p1 = atomicAdd(&g_cursor[d4.y], 1);
        int p2 = atomicAdd(&g_cursor[d4.z], 1);
        int p3 = atomicAdd(&g_cursor[d4.w], 1);
        g_csrc[p0] = s4.x;
        g_csrc[p1] = s4.y;
        g_csrc[p2] = s4.z;
        g_csrc[p3] = s4.w;
    } else {
        for (int e = base; e < E; e++) {
            int d = ei[E + e];
            int pos = atomicAdd(&g_cursor[d], 1);
            g_csrc[pos] = ei[e];
        }
    }
}

// ---------------- fused softmax + aggregate + bias + LayerNorm -------------
// (R10 version — best measured configuration)
__global__ __launch_bounds__(256) void agg_kernel(float* __restrict__ out,
                                                  const float* __restrict__ bias,
                                                  const float* __restrict__ gamma,
                                                  const float* __restrict__ beta,
                                                  int N) {
    __shared__ float s_e[8][CAPN * 4];   // per-warp alpha cache (16 KB)
    __shared__ int   s_i[8][CAPN];       // per-warp index cache (4 KB)

    int gtid = blockIdx.x * blockDim.x + threadIdx.x;
    int node = gtid >> 5;
    int lane = gtid & 31;
    int warp = (threadIdx.x) >> 5;
    if (node >= N) return;
    float* se = s_e[warp];
    int*   si = s_i[warp];

    int beg = g_rowstart[node];
    int deg = g_deg[node];

    float4 ad4 = *(const float4*)(g_adst + (size_t)node * H);
    float adh[4] = {ad4.x, ad4.y, ad4.z, ad4.w};

    // ---- pass 1: exp(logit)+index -> smem, accumulate denominators --------
    float s[4] = {0.f, 0.f, 0.f, 0.f};
    for (int i = lane; i < deg; i += 32) {
        int src = g_csrc[beg + i];
        float4 as = *(const float4*)(g_asrc + (size_t)src * H);
        float e0 = __expf(leaky(as.x + adh[0]));
        float e1 = __expf(leaky(as.y + adh[1]));
        float e2 = __expf(leaky(as.z + adh[2]));
        float e3 = __expf(leaky(as.w + adh[3]));
        if (i < CAPN) {
            *(float4*)(se + i * 4) = make_float4(e0, e1, e2, e3);
            si[i] = src;
        }
        s[0] += e0; s[1] += e1; s[2] += e2; s[3] += e3;
    }
#pragma unroll
    for (int h = 0; h < 4; h++) {
#pragma unroll
        for (int off = 16; off > 0; off >>= 1)
            s[h] += __shfl_xor_sync(0xffffffff, s[h], off);
    }
    __syncwarp();

    int h = lane >> 3;
    float invS = 1.0f / (s[h] + 1e-16f);
    float adsh = adh[h];
    int ch = lane * 4;

    int dc = deg < CAPN ? deg : CAPN;

    // ---- pass 2: weighted gather-accumulate (8-wide unroll, smem indices) -
    float4 acc = make_float4(0.f, 0.f, 0.f, 0.f);
    int i = 0;
    for (; i + 8 <= dc; i += 8) {
        int   idx[8];
        float al[8];
        uint2 r[8];
#pragma unroll
        for (int j = 0; j < 8; j++) {
            idx[j] = si[i + j];
            al[j]  = se[(i + j) * 4 + h];
        }
#pragma unroll
        for (int j = 0; j < 8; j++)
            r[j] = *(const uint2*)(g_xwh + (size_t)idx[j] * HC + ch);
#pragma unroll
        for (int j = 0; j < 8; j++) {
            float2 fa = __half22float2(*(__half2*)&r[j].x);
            float2 fb = __half22float2(*(__half2*)&r[j].y);
            acc.x = fmaf(al[j], fa.x, acc.x);
            acc.y = fmaf(al[j], fa.y, acc.y);
            acc.z = fmaf(al[j], fb.x, acc.z);
            acc.w = fmaf(al[j], fb.y, acc.w);
        }
    }
    for (; i < dc; i++) {
        int src = si[i];
        float a0 = se[i * 4 + h];
        uint2 r0 = *(const uint2*)(g_xwh + (size_t)src * HC + ch);
        float2 fa = __half22float2(*(__half2*)&r0.x);
        float2 fb = __half22float2(*(__half2*)&r0.y);
        acc.x = fmaf(a0, fa.x, acc.x);
        acc.y = fmaf(a0, fa.y, acc.y);
        acc.z = fmaf(a0, fb.x, acc.z);
        acc.w = fmaf(a0, fb.y, acc.w);
    }
    // spill path (deg > CAPN): recompute alpha from asrc
    for (; i < deg; i++) {
        int src = g_csrc[beg + i];
        float a = g_asrc[(size_t)src * H + h];
        float a0 = __expf(leaky(a + adsh));
        uint2 r0 = *(const uint2*)(g_xwh + (size_t)src * HC + ch);
        float2 fa = __half22float2(*(__half2*)&r0.x);
        float2 fb = __half22float2(*(__half2*)&r0.y);
        acc.x = fmaf(a0, fa.x, acc.x);
        acc.y = fmaf(a0, fa.y, acc.y);
        acc.z = fmaf(a0, fb.x, acc.z);
        acc.w = fmaf(a0, fb.y, acc.w);
    }

    // normalize by softmax denominator
    acc.x *= invS; acc.y *= invS; acc.z *= invS; acc.w *= invS;

    // ---- epilogue: + bias, LayerNorm, write ------------------------------
    float4 b4 = *(const float4*)(bias + ch);
    acc.x += b4.x; acc.y += b4.y; acc.z += b4.z; acc.w += b4.w;

    float sum = acc.x + acc.y + acc.z + acc.w;
    float sq  = acc.x * acc.x + acc.y * acc.y + acc.z * acc.z + acc.w * acc.w;
#pragma unroll
    for (int off = 16; off > 0; off >>= 1) {
        sum += __shfl_xor_sync(0xffffffff, sum, off);
        sq  += __shfl_xor_sync(0xffffffff, sq,  off);
    }
    float mean = sum * (1.0f / HC);
    float var  = sq * (1.0f / HC) - mean * mean;
    float rstd = rsqrtf(var + LN_EPS);

    float4 g4 = *(const float4*)(gamma + ch);
    float4 be = *(const float4*)(beta + ch);
    acc.x = g4.x * (acc.x - mean) * rstd + be.x;
    acc.y = g4.y * (acc.y - mean) * rstd + be.y;
    acc.z = g4.z * (acc.z - mean) * rstd + be.z;
    acc.w = g4.w * (acc.w - mean) * rstd + be.w;
    *(float4*)(out + (size_t)node * HC + ch) = acc;
}

// ---------------- launch -----------------------------------------------------
// CSR build chain runs on a forked side stream, concurrent with the GEMM on
// the main stream; the two join before agg.
extern "C" void kernel_launch(void* const* d_in, const int* in_sizes, int n_in,
                              void* d_out, int out_size) {
    const float* x       = (const float*)d_in[0];
    const int*   ei      = (const int*)d_in[1];   // edge_index (int32 on the wire)
    // d_in[2] = edge_weight (unused by the reference computation)
    const float* W       = (const float*)d_in[3];
    const float* att_src = (const float*)d_in[4];
    const float* att_dst = (const float*)d_in[5];
    const float* bias    = (const float*)d_in[6];
    const float* gamma   = (const float*)d_in[7];
    const float* beta    = (const float*)d_in[8];
    float* out = (float*)d_out;

    int N = in_sizes[0] / IN_DIM;
    int E = in_sizes[2];            // edge_weight has E elements
    int nB = (N + 255) / 256;       // scan blocks (<=512)
    int e4B = (E / 4 + 256) / 256;  // 4-wide edge kernels (covers tail)

    cudaStream_t s2;
    cudaEvent_t evFork, evJoin;
    cudaStreamCreateWithFlags(&s2, cudaStreamNonBlocking);
    cudaEventCreateWithFlags(&evFork, cudaEventDisableTiming);
    cudaEventCreateWithFlags(&evJoin, cudaEventDisableTiming);

    // fork: side stream depends on prior work in the main stream
    cudaEventRecord(evFork, 0);
    cudaStreamWaitEvent(s2, evFork, 0);

    // CSR chain on s2 (independent of GEMM)
    hist_init_kernel<<<nB, 256, 0, s2>>>(N);                          // 1
    hist_kernel<<<e4B, 256, 0, s2>>>(ei, E);                          // 2
    scan1_kernel<<<nB, 256, 0, s2>>>(N);                              // 3
    // GEMM on main stream (submission #4 -> ncu capture window)
    gemm_att_kernel<<<(N + 127) / 128, 256>>>(x, W, att_src, att_dst, N);
    scan2_kernel<<<1, 512, 0, s2>>>(nB);                              // 5
    scan3_kernel<<<nB, 256, 0, s2>>>(N);                              // 6
    fill_kernel<<<e4B, 256, 0, s2>>>(ei, E);                          // 7
    cudaEventRecord(evJoin, s2);

    // join: agg needs both the GEMM outputs and the CSR structure
    cudaStreamWaitEvent(0, evJoin, 0);
    {
        long long threads = (long long)N * 32;
        agg_kernel<<<(unsigned)((threads + 255) / 256), 256>>>(out, bias, gamma, beta, N);  // 8
    }
}